// round 13
// baseline (speedup 1.0000x reference)
#include <cuda_runtime.h>
#include <math.h>
#include <stdint.h>

#define EMBED 768
#define NH    12
#define HD    64
#define BATCH 4
#define SEQ   2048
#define MROWS (BATCH*SEQ)   // 8192

// fp32 scratch
__device__ float g_q[BATCH*NH*SEQ*HD];
__device__ float g_k[BATCH*NH*SEQ*HD];
__device__ float g_v[BATCH*NH*SEQ*HD];
__device__ float g_ctx[MROWS*EMBED];

// Pre-split bf16 hi/lo planes, frag-permuted (u32 = bf16x2)
#define XPL (64*24*2048)   // A-frag planes: 64 m-tiles x 24 slabs
#define WPL (6*24*2048)    // B-frag planes: 6 n-tiles x 24 slabs
#define KPL (48*32*2048)   // attn planes: 48 bh x 32 tiles
__device__ uint32_t g_xH[XPL],  g_xL[XPL];
__device__ uint32_t g_wH4[4*WPL], g_wL4[4*WPL];
__device__ uint32_t g_cH[XPL],  g_cL[XPL];
__device__ uint32_t g_kHp[KPL], g_kLp[KPL], g_vHp[KPL], g_vLp[KPL];

typedef unsigned long long ull;

// ---------------- mma.sync bf16 helpers ----------------
__device__ __forceinline__ void bf16_split2(float x, float y,
                                            uint32_t &h2, uint32_t &l2) {
    asm("cvt.rn.bf16x2.f32 %0, %1, %2;" : "=r"(h2) : "f"(y), "f"(x));
    float hx = __uint_as_float(h2 << 16);
    float hy = __uint_as_float(h2 & 0xFFFF0000u);
    asm("cvt.rn.bf16x2.f32 %0, %1, %2;" : "=r"(l2) : "f"(y - hy), "f"(x - hx));
}
__device__ __forceinline__ void mma_bf16(float (&c)[4],
                                         uint32_t a0, uint32_t a1,
                                         uint32_t a2, uint32_t a3,
                                         uint32_t b0, uint32_t b1) {
    asm("mma.sync.aligned.m16n8k16.row.col.f32.bf16.bf16.f32 "
        "{%0,%1,%2,%3}, {%4,%5,%6,%7}, {%8,%9}, {%0,%1,%2,%3};"
        : "+f"(c[0]), "+f"(c[1]), "+f"(c[2]), "+f"(c[3])
        : "r"(a0), "r"(a1), "r"(a2), "r"(a3), "r"(b0), "r"(b1));
}
__device__ __forceinline__ void cp_async16(uint32_t saddr, const void* g) {
    asm volatile("cp.async.cg.shared.global [%0], [%1], 16;"
                 :: "r"(saddr), "l"(g) : "memory");
}
#define CP_COMMIT() asm volatile("cp.async.commit_group;" ::: "memory")
#define CP_WAIT0()  asm volatile("cp.async.wait_group 0;" ::: "memory")

// ---------------------------------------------------------------------------
// Converters: fp32 -> frag-permuted hi/lo bf16x2 planes.
// ---------------------------------------------------------------------------
__global__ __launch_bounds__(192) void conv_afrag_kernel(
    const float* __restrict__ src_in, int which)
{
    const float* src = which ? (const float*)g_ctx : src_in;
    uint32_t* H = which ? g_cH : g_xH;
    uint32_t* L = which ? g_cL : g_xL;

    const int row_g = blockIdx.x;          // 0..8191
    const int k = threadIdx.x * 4;         // 0..764
    float4 v = *(const float4*)(src + (size_t)row_g * EMBED + k);

    const int s = k >> 5;
    const int row = row_g & 127;
    uint32_t* Hp = H + ((size_t)(row_g >> 7) * 24 + s) * 2048;
    uint32_t* Lp = L + ((size_t)(row_g >> 7) * 24 + s) * 2048;

    const int k4 = k & 31;
    const int ks = k4 >> 4, kk = k4 & 15;
    const int hk = kk >> 3, t0 = (kk & 7) >> 1;
    const int g = row & 7, hm = (row >> 3) & 1, mt = row >> 4;
    const int idx  = (hm + 2 * hk) ^ ks;
    const int base = (ks * 8 + mt) * 128 + idx;
    uint32_t h2, l2;
    bf16_split2(v.x, v.y, h2, l2);
    int sl = g * 4 + t0;  int sp = sl ^ ((sl >> 3) & 1);
    Hp[base + sp * 4] = h2;  Lp[base + sp * 4] = l2;
    bf16_split2(v.z, v.w, h2, l2);
    sl = g * 4 + t0 + 1;  sp = sl ^ ((sl >> 3) & 1);
    Hp[base + sp * 4] = h2;  Lp[base + sp * 4] = l2;
}

__global__ __launch_bounds__(192) void conv_bfrag_kernel(
    const float* __restrict__ src, int z)
{
    const int row_g = blockIdx.x;          // 0..767
    const int k = threadIdx.x * 4;
    float4 v = *(const float4*)(src + (size_t)row_g * EMBED + k);

    const int s = k >> 5;
    const int row = row_g & 127;
    const size_t po = ((size_t)z * 6 + (row_g >> 7)) * 24 + s;
    uint32_t* Hp = g_wH4 + po * 2048;
    uint32_t* Lp = g_wL4 + po * 2048;

    const int k4 = k & 31;
    const int ks = k4 >> 4, kk = k4 & 15;
    const int hk = kk >> 3, t0 = (kk & 7) >> 1;
    const int gn = row & 7, nt = row >> 3;
    const int base = (ks * 16 + nt) * 64 + hk;
    uint32_t h2, l2;
    bf16_split2(v.x, v.y, h2, l2);
    int sl = gn * 4 + t0;
    int sp = (sl ^ ((sl >> 3) & 1)) ^ (ks << 3);
    Hp[base + sp * 2] = h2;  Lp[base + sp * 2] = l2;
    bf16_split2(v.z, v.w, h2, l2);
    sl = gn * 4 + t0 + 1;
    sp = (sl ^ ((sl >> 3) & 1)) ^ (ks << 3);
    Hp[base + sp * 2] = h2;  Lp[base + sp * 2] = l2;
}

__global__ __launch_bounds__(256) void conv_kv_kernel()
{
    const int kt = blockIdx.x;             // 0..31
    const int bh = blockIdx.y;             // 0..47
    const int tid = threadIdx.x;
    const int ct = kt * 64;
    const size_t gbase = (size_t)bh * SEQ * HD;
    const uint32_t toff = ((uint32_t)bh * 32 + kt) * 2048;
    uint32_t* KH = g_kHp + toff;  uint32_t* KL = g_kLp + toff;
    uint32_t* VH = g_vHp + toff;  uint32_t* VL = g_vLp + toff;

    #pragma unroll
    for (int it = 0; it < 4; it++) {
        const int f  = it * 256 + tid;
        const int r  = f >> 4;
        const int k4 = (f & 15) * 4;
        float4 v = *(const float4*)(g_k + gbase + (size_t)(ct + r) * HD + k4);
        const int nt = r >> 3, gn = r & 7;
        const int ks = k4 >> 4, kk = k4 & 15;
        const int khalf = kk >> 3, t0 = (kk & 7) >> 1;
        const int base = (ks * 8 + nt) * 64 + khalf;
        uint32_t h2, l2;
        bf16_split2(v.x, v.y, h2, l2);
        int sl = gn * 4 + t0;
        int sp = (sl ^ ((sl >> 3) & 1)) ^ (ks << 3);
        KH[base + sp * 2] = h2;  KL[base + sp * 2] = l2;
        bf16_split2(v.z, v.w, h2, l2);
        sl = gn * 4 + t0 + 1;
        sp = (sl ^ ((sl >> 3) & 1)) ^ (ks << 3);
        KH[base + sp * 2] = h2;  KL[base + sp * 2] = l2;
    }
    #pragma unroll
    for (int it = 0; it < 2; it++) {
        const int f  = it * 256 + tid;
        const int cp = f >> 4;
        const int dq = (f & 15) * 4;
        const int c0 = cp * 2;
        float4 v0 = *(const float4*)(g_v + gbase + (size_t)(ct + c0)     * HD + dq);
        float4 v1 = *(const float4*)(g_v + gbase + (size_t)(ct + c0 + 1) * HD + dq);
        const int ks = c0 >> 4, kc = c0 & 15;
        const int khalf = kc >> 3, tt = (kc & 7) >> 1;
        const float* a0 = (const float*)&v0;
        const float* a1 = (const float*)&v1;
        #pragma unroll
        for (int j = 0; j < 4; j++) {
            const int d = dq + j;
            const int nt = d >> 3, gn = d & 7;
            const int sl = gn * 4 + tt;
            const int sp = ((sl ^ ((sl >> 3) & 1)) ^ (ks << 3)) ^ nt;
            const int addr = (ks * 8 + nt) * 64 + khalf + sp * 2;
            uint32_t h2, l2;
            bf16_split2(a0[j], a1[j], h2, l2);
            VH[addr] = h2;  VL[addr] = l2;
        }
    }
}

// ---------------------------------------------------------------------------
// Tensor-core GEMM with copy-staging from pre-split planes (R12, passing).
// ---------------------------------------------------------------------------
#define NSLAB (EMBED/32)   // 24

__device__ __forceinline__ void gemm_mma_slab(const uint32_t* __restrict__ SB,
                                              int wr, int wc, int lp,
                                              float C[4][4][4])
{
    const uint32_t* AH = SB;
    const uint32_t* AL = SB + 2048;
    const uint32_t* BH = SB + 4096;
    const uint32_t* BL = SB + 6144;
    #pragma unroll
    for (int ks = 0; ks < 2; ks++) {
        uint4 ah[4], al4[4];
        uint2 bh[4], bl4[4];
        #pragma unroll
        for (int mt = 0; mt < 4; mt++) {
            const int off = (ks * 8 + wr * 4 + mt) * 128 + lp * 4;
            ah[mt]  = *(const uint4*)&AH[off];
            al4[mt] = *(const uint4*)&AL[off];
        }
        const int lpb = lp ^ (ks << 3);
        #pragma unroll
        for (int nt = 0; nt < 4; nt++) {
            const int off = (ks * 16 + wc * 4 + nt) * 64 + lpb * 2;
            bh[nt]  = *(const uint2*)&BH[off];
            bl4[nt] = *(const uint2*)&BL[off];
        }
        #pragma unroll
        for (int mt = 0; mt < 4; mt++) {
            const uint32_t a0 = ks ? ah[mt].y  : ah[mt].x;
            const uint32_t a1 = ks ? ah[mt].x  : ah[mt].y;
            const uint32_t a2 = ks ? ah[mt].w  : ah[mt].z;
            const uint32_t a3 = ks ? ah[mt].z  : ah[mt].w;
            const uint32_t e0 = ks ? al4[mt].y : al4[mt].x;
            const uint32_t e1 = ks ? al4[mt].x : al4[mt].y;
            const uint32_t e2 = ks ? al4[mt].w : al4[mt].z;
            const uint32_t e3 = ks ? al4[mt].z : al4[mt].w;
            #pragma unroll
            for (int nt = 0; nt < 4; nt++) {
                mma_bf16(C[mt][nt], a0, a1, a2, a3, bh[nt].x, bh[nt].y);
                mma_bf16(C[mt][nt], e0, e1, e2, e3, bh[nt].x, bh[nt].y);
                mma_bf16(C[mt][nt], a0, a1, a2, a3, bl4[nt].x, bl4[nt].y);
            }
        }
    }
}

#define GEMM_LD(s) do {                                              \
    const uint4* _a = (const uint4*)(AHg + (s) * 2048);              \
    const uint4* _b = (const uint4*)(ALg + (s) * 2048);              \
    const uint4* _c = (const uint4*)(BHg + (s) * 2048);              \
    const uint4* _d = (const uint4*)(BLg + (s) * 2048);              \
    r0 = _a[tid]; r1 = _a[tid + 256];                                \
    r2 = _b[tid]; r3 = _b[tid + 256];                                \
    r4 = _c[tid]; r5 = _c[tid + 256];                                \
    r6 = _d[tid]; r7 = _d[tid + 256];                                \
} while (0)
#define GEMM_ST() do {                                               \
    uint4* _d = (uint4*)SB;                                          \
    _d[tid] = r0;        _d[tid + 256] = r1;                         \
    _d[512 + tid] = r2;  _d[512 + tid + 256] = r3;                   \
    _d[1024 + tid] = r4; _d[1024 + tid + 256] = r5;                  \
    _d[1536 + tid] = r6; _d[1536 + tid + 256] = r7;                  \
} while (0)

__device__ __forceinline__ void mma_gemm_mainloop_pl(
    const uint32_t* __restrict__ AHg, const uint32_t* __restrict__ ALg,
    const uint32_t* __restrict__ BHg, const uint32_t* __restrict__ BLg,
    uint32_t* __restrict__ SB, float C[4][4][4])
{
    const int tid  = threadIdx.x;
    const int lane = tid & 31;
    const int wid  = tid >> 5;
    const int wr   = wid >> 2;
    const int wc   = wid & 3;
    const int lp   = lane ^ ((lane >> 3) & 1);

    uint4 r0, r1, r2, r3, r4, r5, r6, r7;
    GEMM_LD(0);
    #pragma unroll 1
    for (int s = 0; s < NSLAB; s++) {
        __syncthreads();
        GEMM_ST();
        __syncthreads();
        if (s + 1 < NSLAB) GEMM_LD(s + 1);
        gemm_mma_slab(SB, wr, wc, lp, C);
    }
}

__global__ __launch_bounds__(256) void qkv_mma_kernel(
    const float* __restrict__ bq, const float* __restrict__ bk,
    const float* __restrict__ bv)
{
    __shared__ uint32_t SB[8192];
    const int z = blockIdx.z;
    const float* bias = (z == 0) ? bq : (z == 1) ? bk : bv;
    float* dst = (z == 0) ? g_q : (z == 1) ? g_k : g_v;

    const int m0 = blockIdx.y * 128;
    const int n0 = blockIdx.x * 128;
    const uint32_t* AHg = g_xH + ((size_t)blockIdx.y * 24) * 2048;
    const uint32_t* ALg = g_xL + ((size_t)blockIdx.y * 24) * 2048;
    const size_t bo_ = (((size_t)z * 6 + blockIdx.x) * 24) * 2048;
    const uint32_t* BHg = g_wH4 + bo_;
    const uint32_t* BLg = g_wL4 + bo_;

    float C[4][4][4];
    #pragma unroll
    for (int mt = 0; mt < 4; mt++)
        #pragma unroll
        for (int nt = 0; nt < 4; nt++)
            #pragma unroll
            for (int q = 0; q < 4; q++) C[mt][nt][q] = 0.f;

    mma_gemm_mainloop_pl(AHg, ALg, BHg, BLg, SB, C);

    const int lane = threadIdx.x & 31;
    const int wid  = threadIdx.x >> 5;
    const int wr = wid >> 2, wc = wid & 3;
    const int g = lane >> 2, t = lane & 3;
    #pragma unroll
    for (int mt = 0; mt < 4; mt++) {
        #pragma unroll
        for (int nt = 0; nt < 4; nt++) {
            const int c = n0 + wc * 32 + nt * 8 + t * 2;
            const int h = c >> 6, d = c & 63;
            const float2 bv2 = *(const float2*)(bias + c);
            #pragma unroll
            for (int half = 0; half < 2; half++) {
                const int m = m0 + wr * 64 + mt * 16 + g + half * 8;
                const int b = m >> 11;
                const int n = m & 2047;
                float2 o;
                o.x = C[mt][nt][half * 2 + 0] + bv2.x;
                o.y = C[mt][nt][half * 2 + 1] + bv2.y;
                *(float2*)&dst[(((size_t)(b * NH + h) * SEQ) + n) * HD + d] = o;
            }
        }
    }
}

__global__ __launch_bounds__(256) void out_mma_kernel(
    const float* __restrict__ bo, float* __restrict__ out)
{
    __shared__ uint32_t SB[8192];
    const int m0 = blockIdx.y * 128;
    const int n0 = blockIdx.x * 128;
    const uint32_t* AHg = g_cH + ((size_t)blockIdx.y * 24) * 2048;
    const uint32_t* ALg = g_cL + ((size_t)blockIdx.y * 24) * 2048;
    const size_t bo_ = (((size_t)3 * 6 + blockIdx.x) * 24) * 2048;
    const uint32_t* BHg = g_wH4 + bo_;
    const uint32_t* BLg = g_wL4 + bo_;

    float C[4][4][4];
    #pragma unroll
    for (int mt = 0; mt < 4; mt++)
        #pragma unroll
        for (int nt = 0; nt < 4; nt++)
            #pragma unroll
            for (int q = 0; q < 4; q++) C[mt][nt][q] = 0.f;

    mma_gemm_mainloop_pl(AHg, ALg, BHg, BLg, SB, C);

    const int lane = threadIdx.x & 31;
    const int wid  = threadIdx.x >> 5;
    const int wr = wid >> 2, wc = wid & 3;
    const int g = lane >> 2, t = lane & 3;
    #pragma unroll
    for (int mt = 0; mt < 4; mt++) {
        #pragma unroll
        for (int nt = 0; nt < 4; nt++) {
            const int c = n0 + wc * 32 + nt * 8 + t * 2;
            const float2 bv2 = *(const float2*)(bo + c);
            #pragma unroll
            for (int half = 0; half < 2; half++) {
                const int m = m0 + wr * 64 + mt * 16 + g + half * 8;
                float2 o;
                o.x = C[mt][nt][half * 2 + 0] + bv2.x;
                o.y = C[mt][nt][half * 2 + 1] + bv2.y;
                *(float2*)&out[(size_t)m * EMBED + c] = o;
            }
        }
    }
}

// ---------------------------------------------------------------------------
// Flash attention v2: q-block 128 rows, 8 warps, warp owns 16 rows x 64 cols.
// Warp-local softmax (t-lane shuffles only, no barriers), register-direct P
// (S C-frags == PV A-frags), cp.async double-buffered K/V plane copies.
// smem (u32): QH 4096 | QL 4096 | 2 x {KH,KL,VH,VL} x 2048 = 16384 -> 24576
// ---------------------------------------------------------------------------
#define ATT_SMEM (24576 * 4)   // 98304 bytes

__global__ __launch_bounds__(256) void attn_kernel()
{
    extern __shared__ uint32_t smu[];
    uint32_t* QH = smu;
    uint32_t* QL = smu + 4096;
    // KV buffers at smu + 8192 + buf*8192 : KH +0, KL +2048, VH +4096, VL +6144

    const int tid  = threadIdx.x;
    const int lane = tid & 31;
    const int w    = tid >> 5;       // warp 0..7 owns rows 16w..16w+15
    const int g    = lane >> 2;
    const int t    = lane & 3;
    const int lp   = lane ^ ((lane >> 3) & 1);

    const int bh = blockIdx.y;
    const int q0 = blockIdx.x * 128;
    const size_t gbase = (size_t)bh * SEQ * HD;
    const float* Qg = g_q + gbase;

    const uint32_t sbase = (uint32_t)__cvta_generic_to_shared(smu);

    // ---- issue cp.async for tile 0 (overlaps Q staging) ----
    {
        const uint32_t toff = ((uint32_t)bh * 32 + 0) * 2048;
        const uint32_t* gp[4] = { g_kHp + toff, g_kLp + toff,
                                  g_vHp + toff, g_vLp + toff };
        #pragma unroll
        for (int p = 0; p < 4; p++) {
            const uint32_t sd = sbase + (8192 + p * 2048) * 4;
            cp_async16(sd + tid * 16,        gp[p] + tid * 4);
            cp_async16(sd + 4096 + tid * 16, gp[p] + 1024 + tid * 4);
        }
        CP_COMMIT();
    }

    // ---- stage Q (A-frag layout, 128 rows, scale folded) ----
    #pragma unroll
    for (int it = 0; it < 8; it++) {
        const int f  = it * 256 + tid;
        const int r  = f >> 4;
        const int dq = (f & 15) * 4;
        float4 v = *(const float4*)(Qg + (size_t)(q0 + r) * HD + dq);
        v.x *= 0.125f; v.y *= 0.125f; v.z *= 0.125f; v.w *= 0.125f;
        const int mt = r >> 4, row = r & 15;
        const int gg = row & 7, hm = row >> 3;
        const int ks = dq >> 4, kk = dq & 15;
        const int khalf = kk >> 3, t0 = (kk & 7) >> 1;
        const int idx  = (hm + 2 * khalf) ^ ks;
        const int base = (ks * 8 + mt) * 128 + idx;
        uint32_t h2, l2;
        bf16_split2(v.x, v.y, h2, l2);
        int sl = gg * 4 + t0;  int sp = sl ^ ((sl >> 3) & 1);
        QH[base + sp * 4] = h2;  QL[base + sp * 4] = l2;
        bf16_split2(v.z, v.w, h2, l2);
        sl = gg * 4 + t0 + 1;  sp = sl ^ ((sl >> 3) & 1);
        QH[base + sp * 4] = h2;  QL[base + sp * 4] = l2;
    }

    float O[8][4];
    #pragma unroll
    for (int nt = 0; nt < 8; nt++)
        #pragma unroll
        for (int q = 0; q < 4; q++) O[nt][q] = 0.f;
    float mrow0 = -1e30f, mrow1 = -1e30f, lsum0 = 0.f, lsum1 = 0.f;

    #pragma unroll 1
    for (int kt = 0; kt < SEQ / 64; kt++) {
        CP_WAIT0();
        __syncthreads();   // staging of tile kt visible; all warps done with prev buf

        const uint32_t* KB = smu + 8192 + (kt & 1) * 8192;

        // issue cp.async for tile kt+1 into the other buffer
        if (kt + 1 < SEQ / 64) {
            const uint32_t toff = ((uint32_t)bh * 32 + (kt + 1)) * 2048;
            const uint32_t* gp[4] = { g_kHp + toff, g_kLp + toff,
                                      g_vHp + toff, g_vLp + toff };
            const uint32_t bufo = 8192 + ((kt + 1) & 1) * 8192;
            #pragma unroll
            for (int p = 0; p < 4; p++) {
                const uint32_t sd = sbase + (bufo + p * 2048) * 4;
                cp_async16(sd + tid * 16,        gp[p] + tid * 4);
                cp_async16(sd + 4096 + tid * 16, gp[p] + 1024 + tid * 4);
            }
            CP_COMMIT();
        }

        const uint32_t* KH = KB;
        const uint32_t* KL = KB + 2048;
        const uint32_t* VH = KB + 4096;
        const uint32_t* VL = KB + 6144;

        // ---- S = Q K^T (3-term compensated), warp rows 16w..16w+15 ----
        float sS[8][4];
        #pragma unroll
        for (int nt = 0; nt < 8; nt++)
            #pragma unroll
            for (int q = 0; q < 4; q++) sS[nt][q] = 0.f;

        #pragma unroll
        for (int ks = 0; ks < 4; ks++) {
            uint4 qh4 = *(const uint4*)&QH[(ks * 8 + w) * 128 + lp * 4];
            uint4 ql4 = *(const uint4*)&QL[(ks * 8 + w) * 128 + lp * 4];
            const uint32_t* qh = (const uint32_t*)&qh4;
            const uint32_t* ql = (const uint32_t*)&ql4;
            const uint32_t a0 = qh[0 ^ ks], a1 = qh[1 ^ ks];
            const uint32_t a2 = qh[2 ^ ks], a3 = qh[3 ^ ks];
            const uint32_t e0 = ql[0 ^ ks], e1 = ql[1 ^ ks];
            const uint32_t e2 = ql[2 ^ ks], e3 = ql[3 ^ ks];
            const int lpb = lp ^ (ks << 3);
            #pragma unroll
            for (int nt = 0; nt < 8; nt++) {
                uint2 kh = *(const uint2*)&KH[(ks * 8 + nt) * 64 + lpb * 2];
                uint2 kl = *(const uint2*)&KL[(ks * 8 + nt) * 64 + lpb * 2];
                mma_bf16(sS[nt], a0, a1, a2, a3, kh.x, kh.y);
                mma_bf16(sS[nt], e0, e1, e2, e3, kh.x, kh.y);
                mma_bf16(sS[nt], a0, a1, a2, a3, kl.x, kl.y);
            }
        }

        // ---- warp-local online softmax (reduce over t lanes only) ----
        float mx0 = -1e30f, mx1 = -1e30f;
        #pragma unroll
        for (int nt = 0; nt < 8; nt++) {
            mx0 = fmaxf(mx0, fmaxf(sS[nt][0], sS[nt][1]));
            mx1 = fmaxf(mx1, fmaxf(sS[nt][2], sS[nt][3]));
        }
        mx0 = fmaxf(mx0, __shfl_xor_sync(0xffffffffu, mx0, 1, 32));
        mx0 = fmaxf(mx0, __shfl_xor_sync(0xffffffffu, mx0, 2, 32));
        mx1 = fmaxf(mx1, __shfl_xor_sync(0xffffffffu, mx1, 1, 32));
        mx1 = fmaxf(mx1, __shfl_xor_sync(0xffffffffu, mx1, 2, 32));
        const float mn0 = fmaxf(mrow0, mx0), mn1 = fmaxf(mrow1, mx1);
        const float cr0 = __expf(mrow0 - mn0), cr1 = __expf(mrow1 - mn1);
        mrow0 = mn0;  mrow1 = mn1;

        float rs0 = 0.f, rs1 = 0.f;
        #pragma unroll
        for (int nt = 0; nt < 8; nt++) {
            sS[nt][0] = __expf(sS[nt][0] - mn0);
            sS[nt][1] = __expf(sS[nt][1] - mn0);
            sS[nt][2] = __expf(sS[nt][2] - mn1);
            sS[nt][3] = __expf(sS[nt][3] - mn1);
            rs0 += sS[nt][0] + sS[nt][1];
            rs1 += sS[nt][2] + sS[nt][3];
        }
        rs0 += __shfl_xor_sync(0xffffffffu, rs0, 1, 32);
        rs0 += __shfl_xor_sync(0xffffffffu, rs0, 2, 32);
        rs1 += __shfl_xor_sync(0xffffffffu, rs1, 1, 32);
        rs1 += __shfl_xor_sync(0xffffffffu, rs1, 2, 32);
        lsum0 = lsum0 * cr0 + rs0;
        lsum1 = lsum1 * cr1 + rs1;

        #pragma unroll
        for (int nt = 0; nt < 8; nt++) {
            O[nt][0] *= cr0;  O[nt][1] *= cr0;
            O[nt][2] *= cr1;  O[nt][3] *= cr1;
        }

        // ---- O += P V: P straight from S C-frags (register A-frags) ----
        #pragma unroll
        for (int ks = 0; ks < 4; ks++) {
            uint32_t ah0, al0, ah1, al1, ah2, al2, ah3, al3;
            bf16_split2(sS[2*ks][0],   sS[2*ks][1],   ah0, al0);
            bf16_split2(sS[2*ks][2],   sS[2*ks][3],   ah1, al1);
            bf16_split2(sS[2*ks+1][0], sS[2*ks+1][1], ah2, al2);
            bf16_split2(sS[2*ks+1][2], sS[2*ks+1][3], ah3, al3);
            #pragma unroll
            for (int nt = 0; nt < 8; nt++) {
                const int lpv = (lp ^ (ks << 3)) ^ nt;
                uint2 vh = *(const uint2*)&VH[(ks * 8 + nt) * 64 + lpv * 2];
                uint2 vl = *(const uint2*)&VL[(ks * 8 + nt) * 64 + lpv * 2];
                mma_bf16(O[nt], ah0, ah1, ah2, ah3, vh.x, vh.y);
                mma_bf16(O[nt], al0, al1, al2, al3, vh.x, vh.y);
                mma_bf16(O[nt], ah0, ah1, ah2, ah3, vl.x, vl.y);
            }
        }
    }

    // ---- normalize + write context [B,N,C] (c = h*64 + d) ----
    const int b = bh / NH, h = bh % NH;
    const float inv0 = 1.0f / lsum0, inv1 = 1.0f / lsum1;
    const int r0 = q0 + w * 16 + g;
    #pragma unroll
    for (int nt = 0; nt < 8; nt++) {
        const int d = nt * 8 + t * 2;
        float2 o0 = make_float2(O[nt][0] * inv0, O[nt][1] * inv0);
        float2 o1 = make_float2(O[nt][2] * inv1, O[nt][3] * inv1);
        *(float2*)&g_ctx[((size_t)(b * SEQ + r0))     * EMBED + h * HD + d] = o0;
        *(float2*)&g_ctx[((size_t)(b * SEQ + r0 + 8)) * EMBED + h * HD + d] = o1;
    }
}

// ---------------------------------------------------------------------------
extern "C" void kernel_launch(void* const* d_in, const int* in_sizes, int n_in,
                              void* d_out, int out_size)
{
    const float* x  = (const float*)d_in[0];
    const float* Wq = (const float*)d_in[1];
    const float* bq = (const float*)d_in[2];
    const float* Wk = (const float*)d_in[3];
    const float* bk = (const float*)d_in[4];
    const float* Wv = (const float*)d_in[5];
    const float* bv = (const float*)d_in[6];
    const float* Wo = (const float*)d_in[7];
    const float* bo = (const float*)d_in[8];
    float* out = (float*)d_out;

    cudaFuncSetAttribute(attn_kernel,
                         cudaFuncAttributeMaxDynamicSharedMemorySize, ATT_SMEM);

    // pre-split conversions
    conv_afrag_kernel<<<MROWS, 192>>>(x, 0);
    conv_bfrag_kernel<<<EMBED, 192>>>(Wq, 0);
    conv_bfrag_kernel<<<EMBED, 192>>>(Wk, 1);
    conv_bfrag_kernel<<<EMBED, 192>>>(Wv, 2);
    conv_bfrag_kernel<<<EMBED, 192>>>(Wo, 3);

    dim3 gq(EMBED/128, MROWS/128, 3);   // (6, 64, 3)
    qkv_mma_kernel<<<gq, 256>>>(bq, bk, bv);

    dim3 gkv(SEQ/64, BATCH*NH);         // (32, 48)
    conv_kv_kernel<<<gkv, 256>>>();

    dim3 ga(SEQ/128, BATCH*NH);         // (16, 48)
    attn_kernel<<<ga, 256, ATT_SMEM>>>();

    conv_afrag_kernel<<<MROWS, 192>>>(nullptr, 1);

    dim3 go(EMBED/128, MROWS/128);      // (6, 64)
    out_mma_kernel<<<go, 256>>>(bo, out);
}

// round 14
// speedup vs baseline: 1.4407x; 1.4407x over previous
#include <cuda_runtime.h>
#include <math.h>
#include <stdint.h>

#define EMBED 768
#define NH    12
#define HD    64
#define BATCH 4
#define SEQ   2048
#define MROWS (BATCH*SEQ)   // 8192

// fp32 scratch
__device__ float g_q[BATCH*NH*SEQ*HD];
__device__ float g_k[BATCH*NH*SEQ*HD];
__device__ float g_v[BATCH*NH*SEQ*HD];
__device__ float g_ctx[MROWS*EMBED];

// Pre-split bf16 hi/lo planes, frag-permuted (u32 = bf16x2)
#define XPL (64*24*2048)   // A-frag planes: 64 m-tiles x 24 slabs
#define WPL (6*24*2048)    // B-frag planes: 6 n-tiles x 24 slabs
#define KPL (48*32*2048)   // attn planes: 48 bh x 32 tiles
__device__ uint32_t g_xH[XPL],  g_xL[XPL];
__device__ uint32_t g_wH4[4*WPL], g_wL4[4*WPL];
__device__ uint32_t g_cH[XPL],  g_cL[XPL];
__device__ uint32_t g_kHp[KPL], g_kLp[KPL], g_vHp[KPL], g_vLp[KPL];

typedef unsigned long long ull;

// ---------------- mma.sync bf16 helpers ----------------
__device__ __forceinline__ void bf16_split2(float x, float y,
                                            uint32_t &h2, uint32_t &l2) {
    asm("cvt.rn.bf16x2.f32 %0, %1, %2;" : "=r"(h2) : "f"(y), "f"(x));
    float hx = __uint_as_float(h2 << 16);
    float hy = __uint_as_float(h2 & 0xFFFF0000u);
    asm("cvt.rn.bf16x2.f32 %0, %1, %2;" : "=r"(l2) : "f"(y - hy), "f"(x - hx));
}
__device__ __forceinline__ void mma_bf16(float (&c)[4],
                                         uint32_t a0, uint32_t a1,
                                         uint32_t a2, uint32_t a3,
                                         uint32_t b0, uint32_t b1) {
    asm("mma.sync.aligned.m16n8k16.row.col.f32.bf16.bf16.f32 "
        "{%0,%1,%2,%3}, {%4,%5,%6,%7}, {%8,%9}, {%0,%1,%2,%3};"
        : "+f"(c[0]), "+f"(c[1]), "+f"(c[2]), "+f"(c[3])
        : "r"(a0), "r"(a1), "r"(a2), "r"(a3), "r"(b0), "r"(b1));
}
__device__ __forceinline__ void cp_async16(uint32_t saddr, const void* g) {
    asm volatile("cp.async.cg.shared.global [%0], [%1], 16;"
                 :: "r"(saddr), "l"(g) : "memory");
}
#define CP_COMMIT() asm volatile("cp.async.commit_group;" ::: "memory")
#define BAR_PAIR(id) \
    asm volatile("bar.sync %0, 64;" :: "r"(id) : "memory")

// ---------------------------------------------------------------------------
// Converters: fp32 -> frag-permuted hi/lo bf16x2 planes (unchanged, passing).
// ---------------------------------------------------------------------------
__global__ __launch_bounds__(192) void conv_afrag_kernel(
    const float* __restrict__ src_in, int which)
{
    const float* src = which ? (const float*)g_ctx : src_in;
    uint32_t* H = which ? g_cH : g_xH;
    uint32_t* L = which ? g_cL : g_xL;

    const int row_g = blockIdx.x;          // 0..8191
    const int k = threadIdx.x * 4;         // 0..764
    float4 v = *(const float4*)(src + (size_t)row_g * EMBED + k);

    const int s = k >> 5;
    const int row = row_g & 127;
    uint32_t* Hp = H + ((size_t)(row_g >> 7) * 24 + s) * 2048;
    uint32_t* Lp = L + ((size_t)(row_g >> 7) * 24 + s) * 2048;

    const int k4 = k & 31;
    const int ks = k4 >> 4, kk = k4 & 15;
    const int hk = kk >> 3, t0 = (kk & 7) >> 1;
    const int g = row & 7, hm = (row >> 3) & 1, mt = row >> 4;
    const int idx  = (hm + 2 * hk) ^ ks;
    const int base = (ks * 8 + mt) * 128 + idx;
    uint32_t h2, l2;
    bf16_split2(v.x, v.y, h2, l2);
    int sl = g * 4 + t0;  int sp = sl ^ ((sl >> 3) & 1);
    Hp[base + sp * 4] = h2;  Lp[base + sp * 4] = l2;
    bf16_split2(v.z, v.w, h2, l2);
    sl = g * 4 + t0 + 1;  sp = sl ^ ((sl >> 3) & 1);
    Hp[base + sp * 4] = h2;  Lp[base + sp * 4] = l2;
}

__global__ __launch_bounds__(192) void conv_bfrag_kernel(
    const float* __restrict__ src, int z)
{
    const int row_g = blockIdx.x;          // 0..767
    const int k = threadIdx.x * 4;
    float4 v = *(const float4*)(src + (size_t)row_g * EMBED + k);

    const int s = k >> 5;
    const int row = row_g & 127;
    const size_t po = ((size_t)z * 6 + (row_g >> 7)) * 24 + s;
    uint32_t* Hp = g_wH4 + po * 2048;
    uint32_t* Lp = g_wL4 + po * 2048;

    const int k4 = k & 31;
    const int ks = k4 >> 4, kk = k4 & 15;
    const int hk = kk >> 3, t0 = (kk & 7) >> 1;
    const int gn = row & 7, nt = row >> 3;
    const int base = (ks * 16 + nt) * 64 + hk;
    uint32_t h2, l2;
    bf16_split2(v.x, v.y, h2, l2);
    int sl = gn * 4 + t0;
    int sp = (sl ^ ((sl >> 3) & 1)) ^ (ks << 3);
    Hp[base + sp * 2] = h2;  Lp[base + sp * 2] = l2;
    bf16_split2(v.z, v.w, h2, l2);
    sl = gn * 4 + t0 + 1;
    sp = (sl ^ ((sl >> 3) & 1)) ^ (ks << 3);
    Hp[base + sp * 2] = h2;  Lp[base + sp * 2] = l2;
}

__global__ __launch_bounds__(256) void conv_kv_kernel()
{
    const int kt = blockIdx.x;             // 0..31
    const int bh = blockIdx.y;             // 0..47
    const int tid = threadIdx.x;
    const int ct = kt * 64;
    const size_t gbase = (size_t)bh * SEQ * HD;
    const uint32_t toff = ((uint32_t)bh * 32 + kt) * 2048;
    uint32_t* KH = g_kHp + toff;  uint32_t* KL = g_kLp + toff;
    uint32_t* VH = g_vHp + toff;  uint32_t* VL = g_vLp + toff;

    #pragma unroll
    for (int it = 0; it < 4; it++) {
        const int f  = it * 256 + tid;
        const int r  = f >> 4;
        const int k4 = (f & 15) * 4;
        float4 v = *(const float4*)(g_k + gbase + (size_t)(ct + r) * HD + k4);
        const int nt = r >> 3, gn = r & 7;
        const int ks = k4 >> 4, kk = k4 & 15;
        const int khalf = kk >> 3, t0 = (kk & 7) >> 1;
        const int base = (ks * 8 + nt) * 64 + khalf;
        uint32_t h2, l2;
        bf16_split2(v.x, v.y, h2, l2);
        int sl = gn * 4 + t0;
        int sp = (sl ^ ((sl >> 3) & 1)) ^ (ks << 3);
        KH[base + sp * 2] = h2;  KL[base + sp * 2] = l2;
        bf16_split2(v.z, v.w, h2, l2);
        sl = gn * 4 + t0 + 1;
        sp = (sl ^ ((sl >> 3) & 1)) ^ (ks << 3);
        KH[base + sp * 2] = h2;  KL[base + sp * 2] = l2;
    }
    #pragma unroll
    for (int it = 0; it < 2; it++) {
        const int f  = it * 256 + tid;
        const int cp = f >> 4;
        const int dq = (f & 15) * 4;
        const int c0 = cp * 2;
        float4 v0 = *(const float4*)(g_v + gbase + (size_t)(ct + c0)     * HD + dq);
        float4 v1 = *(const float4*)(g_v + gbase + (size_t)(ct + c0 + 1) * HD + dq);
        const int ks = c0 >> 4, kc = c0 & 15;
        const int khalf = kc >> 3, tt = (kc & 7) >> 1;
        const float* a0 = (const float*)&v0;
        const float* a1 = (const float*)&v1;
        #pragma unroll
        for (int j = 0; j < 4; j++) {
            const int d = dq + j;
            const int nt = d >> 3, gn = d & 7;
            const int sl = gn * 4 + tt;
            const int sp = ((sl ^ ((sl >> 3) & 1)) ^ (ks << 3)) ^ nt;
            const int addr = (ks * 8 + nt) * 64 + khalf + sp * 2;
            uint32_t h2, l2;
            bf16_split2(a0[j], a1[j], h2, l2);
            VH[addr] = h2;  VL[addr] = l2;
        }
    }
}

// ---------------------------------------------------------------------------
// Tensor-core GEMM: cp.async double-buffered plane staging.
// Loop: prefetch(s+1) async -> wait(s) -> MMA(s) -> sync.
// ---------------------------------------------------------------------------
#define NSLAB (EMBED/32)   // 24
#define GEMM_SMEM (2 * 8192 * 4)   // 65536 bytes

__device__ __forceinline__ void gemm_mma_slab(const uint32_t* __restrict__ SB,
                                              int wr, int wc, int lp,
                                              float C[4][4][4])
{
    const uint32_t* AH = SB;
    const uint32_t* AL = SB + 2048;
    const uint32_t* BH = SB + 4096;
    const uint32_t* BL = SB + 6144;
    #pragma unroll
    for (int ks = 0; ks < 2; ks++) {
        uint4 ah[4], al4[4];
        uint2 bh[4], bl4[4];
        #pragma unroll
        for (int mt = 0; mt < 4; mt++) {
            const int off = (ks * 8 + wr * 4 + mt) * 128 + lp * 4;
            ah[mt]  = *(const uint4*)&AH[off];
            al4[mt] = *(const uint4*)&AL[off];
        }
        const int lpb = lp ^ (ks << 3);
        #pragma unroll
        for (int nt = 0; nt < 4; nt++) {
            const int off = (ks * 16 + wc * 4 + nt) * 64 + lpb * 2;
            bh[nt]  = *(const uint2*)&BH[off];
            bl4[nt] = *(const uint2*)&BL[off];
        }
        #pragma unroll
        for (int mt = 0; mt < 4; mt++) {
            const uint32_t a0 = ks ? ah[mt].y  : ah[mt].x;
            const uint32_t a1 = ks ? ah[mt].x  : ah[mt].y;
            const uint32_t a2 = ks ? ah[mt].w  : ah[mt].z;
            const uint32_t a3 = ks ? ah[mt].z  : ah[mt].w;
            const uint32_t e0 = ks ? al4[mt].y : al4[mt].x;
            const uint32_t e1 = ks ? al4[mt].x : al4[mt].y;
            const uint32_t e2 = ks ? al4[mt].w : al4[mt].z;
            const uint32_t e3 = ks ? al4[mt].z : al4[mt].w;
            #pragma unroll
            for (int nt = 0; nt < 4; nt++) {
                mma_bf16(C[mt][nt], a0, a1, a2, a3, bh[nt].x, bh[nt].y);
                mma_bf16(C[mt][nt], e0, e1, e2, e3, bh[nt].x, bh[nt].y);
                mma_bf16(C[mt][nt], a0, a1, a2, a3, bl4[nt].x, bl4[nt].y);
            }
        }
    }
}

// Issue async copy of slab s (4 planes x 8KB) into buffer buf.
#define GEMM_PREF(s, buf) do {                                             \
    const uint32_t _sd = sbase + (buf) * 32768;                            \
    cp_async16(_sd +     0 + tid * 16, AHg + (s) * 2048 + tid * 4);        \
    cp_async16(_sd +  4096 + tid * 16, AHg + (s) * 2048 + 1024 + tid * 4); \
    cp_async16(_sd +  8192 + tid * 16, ALg + (s) * 2048 + tid * 4);        \
    cp_async16(_sd + 12288 + tid * 16, ALg + (s) * 2048 + 1024 + tid * 4); \
    cp_async16(_sd + 16384 + tid * 16, BHg + (s) * 2048 + tid * 4);        \
    cp_async16(_sd + 20480 + tid * 16, BHg + (s) * 2048 + 1024 + tid * 4); \
    cp_async16(_sd + 24576 + tid * 16, BLg + (s) * 2048 + tid * 4);        \
    cp_async16(_sd + 28672 + tid * 16, BLg + (s) * 2048 + 1024 + tid * 4); \
    CP_COMMIT();                                                           \
} while (0)

__device__ __forceinline__ void mma_gemm_mainloop_pl(
    const uint32_t* __restrict__ AHg, const uint32_t* __restrict__ ALg,
    const uint32_t* __restrict__ BHg, const uint32_t* __restrict__ BLg,
    uint32_t* __restrict__ SB, float C[4][4][4])
{
    const int tid  = threadIdx.x;
    const int lane = tid & 31;
    const int wid  = tid >> 5;
    const int wr   = wid >> 2;
    const int wc   = wid & 3;
    const int lp   = lane ^ ((lane >> 3) & 1);
    const uint32_t sbase = (uint32_t)__cvta_generic_to_shared(SB);

    GEMM_PREF(0, 0);
    #pragma unroll 1
    for (int s = 0; s < NSLAB; s++) {
        if (s + 1 < NSLAB) {
            GEMM_PREF(s + 1, (s + 1) & 1);
            asm volatile("cp.async.wait_group 1;" ::: "memory");
        } else {
            asm volatile("cp.async.wait_group 0;" ::: "memory");
        }
        __syncthreads();           // slab s visible to all warps
        gemm_mma_slab(SB + (s & 1) * 8192, wr, wc, lp, C);
        __syncthreads();           // all done with buf s&1 before s+2 prefetch
    }
}

__global__ __launch_bounds__(256) void qkv_mma_kernel(
    const float* __restrict__ bq, const float* __restrict__ bk,
    const float* __restrict__ bv)
{
    extern __shared__ uint32_t SB[];
    const int z = blockIdx.z;
    const float* bias = (z == 0) ? bq : (z == 1) ? bk : bv;
    float* dst = (z == 0) ? g_q : (z == 1) ? g_k : g_v;

    const int m0 = blockIdx.y * 128;
    const int n0 = blockIdx.x * 128;
    const uint32_t* AHg = g_xH + ((size_t)blockIdx.y * 24) * 2048;
    const uint32_t* ALg = g_xL + ((size_t)blockIdx.y * 24) * 2048;
    const size_t bo_ = (((size_t)z * 6 + blockIdx.x) * 24) * 2048;
    const uint32_t* BHg = g_wH4 + bo_;
    const uint32_t* BLg = g_wL4 + bo_;

    float C[4][4][4];
    #pragma unroll
    for (int mt = 0; mt < 4; mt++)
        #pragma unroll
        for (int nt = 0; nt < 4; nt++)
            #pragma unroll
            for (int q = 0; q < 4; q++) C[mt][nt][q] = 0.f;

    mma_gemm_mainloop_pl(AHg, ALg, BHg, BLg, SB, C);

    const int lane = threadIdx.x & 31;
    const int wid  = threadIdx.x >> 5;
    const int wr = wid >> 2, wc = wid & 3;
    const int g = lane >> 2, t = lane & 3;
    #pragma unroll
    for (int mt = 0; mt < 4; mt++) {
        #pragma unroll
        for (int nt = 0; nt < 4; nt++) {
            const int c = n0 + wc * 32 + nt * 8 + t * 2;
            const int h = c >> 6, d = c & 63;
            const float2 bv2 = *(const float2*)(bias + c);
            #pragma unroll
            for (int half = 0; half < 2; half++) {
                const int m = m0 + wr * 64 + mt * 16 + g + half * 8;
                const int b = m >> 11;
                const int n = m & 2047;
                float2 o;
                o.x = C[mt][nt][half * 2 + 0] + bv2.x;
                o.y = C[mt][nt][half * 2 + 1] + bv2.y;
                *(float2*)&dst[(((size_t)(b * NH + h) * SEQ) + n) * HD + d] = o;
            }
        }
    }
}

__global__ __launch_bounds__(256) void out_mma_kernel(
    const float* __restrict__ bo, float* __restrict__ out)
{
    extern __shared__ uint32_t SB[];
    const int m0 = blockIdx.y * 128;
    const int n0 = blockIdx.x * 128;
    const uint32_t* AHg = g_cH + ((size_t)blockIdx.y * 24) * 2048;
    const uint32_t* ALg = g_cL + ((size_t)blockIdx.y * 24) * 2048;
    const size_t bo_ = (((size_t)3 * 6 + blockIdx.x) * 24) * 2048;
    const uint32_t* BHg = g_wH4 + bo_;
    const uint32_t* BLg = g_wL4 + bo_;

    float C[4][4][4];
    #pragma unroll
    for (int mt = 0; mt < 4; mt++)
        #pragma unroll
        for (int nt = 0; nt < 4; nt++)
            #pragma unroll
            for (int q = 0; q < 4; q++) C[mt][nt][q] = 0.f;

    mma_gemm_mainloop_pl(AHg, ALg, BHg, BLg, SB, C);

    const int lane = threadIdx.x & 31;
    const int wid  = threadIdx.x >> 5;
    const int wr = wid >> 2, wc = wid & 3;
    const int g = lane >> 2, t = lane & 3;
    #pragma unroll
    for (int mt = 0; mt < 4; mt++) {
        #pragma unroll
        for (int nt = 0; nt < 4; nt++) {
            const int c = n0 + wc * 32 + nt * 8 + t * 2;
            const float2 bv2 = *(const float2*)(bo + c);
            #pragma unroll
            for (int half = 0; half < 2; half++) {
                const int m = m0 + wr * 64 + mt * 16 + g + half * 8;
                float2 o;
                o.x = C[mt][nt][half * 2 + 0] + bv2.x;
                o.y = C[mt][nt][half * 2 + 1] + bv2.y;
                *(float2*)&out[(size_t)m * EMBED + c] = o;
            }
        }
    }
}

// ---------------------------------------------------------------------------
// Flash attention on mma.sync bf16 (R12 version verbatim — best passing).
// ---------------------------------------------------------------------------
#define ATT_SMEM ((8*2048 + 256) * 4)   // 66560 bytes

__global__ __launch_bounds__(256, 2) void attn_kernel()
{
    extern __shared__ uint32_t smu[];
    uint32_t* QH = smu;
    uint32_t* QL = smu + 2048;
    uint32_t* KH = smu + 4096;
    uint32_t* KL = smu + 6144;
    uint32_t* VH = smu + 8192;
    uint32_t* VL = smu + 10240;
    uint32_t* PH = smu + 12288;
    uint32_t* PL = smu + 14336;
    float* smax  = (float*)(smu + 16384);   // [2][64]
    float* ssum  = smax + 128;              // [2][64]

    const int tid  = threadIdx.x;
    const int lane = tid & 31;
    const int wid  = tid >> 5;
    const int wr   = wid >> 1;
    const int wc   = wid & 1;
    const int g    = lane >> 2;
    const int t    = lane & 3;
    const int lp   = lane ^ ((lane >> 3) & 1);

    const int bh = blockIdx.y;
    const int q0 = blockIdx.x * 64;
    const size_t gbase = (size_t)bh * SEQ * HD;
    const float* Qg = g_q + gbase;

    // ---- stage Q once (A-frag layout, 0.125 scale folded in) ----
    #pragma unroll
    for (int it = 0; it < 4; it++) {
        const int f  = it * 256 + tid;
        const int r  = f >> 4;
        const int dq = (f & 15) * 4;
        float4 v = *(const float4*)(Qg + (size_t)(q0 + r) * HD + dq);
        v.x *= 0.125f; v.y *= 0.125f; v.z *= 0.125f; v.w *= 0.125f;
        const int mt = r >> 4, row = r & 15;
        const int gg = row & 7, hm = row >> 3;
        const int ks = dq >> 4, kk = dq & 15;
        const int khalf = kk >> 3, t0 = (kk & 7) >> 1;
        const int idx  = (hm + 2 * khalf) ^ ks;
        const int base = (ks * 4 + mt) * 128 + idx;
        uint32_t h2, l2;
        bf16_split2(v.x, v.y, h2, l2);
        int sl = gg * 4 + t0;  int sp = sl ^ ((sl >> 3) & 1);
        QH[base + sp * 4] = h2;  QL[base + sp * 4] = l2;
        bf16_split2(v.z, v.w, h2, l2);
        sl = gg * 4 + t0 + 1;  sp = sl ^ ((sl >> 3) & 1);
        QH[base + sp * 4] = h2;  QL[base + sp * 4] = l2;
    }

    float O[4][4];
    #pragma unroll
    for (int nt = 0; nt < 4; nt++)
        #pragma unroll
        for (int q = 0; q < 4; q++) O[nt][q] = 0.f;
    float mrow0 = -1e30f, mrow1 = -1e30f, lsum0 = 0.f, lsum1 = 0.f;

    #pragma unroll 1
    for (int kt = 0; kt < SEQ / 64; kt++) {
        __syncthreads();    // prev tile's mma done before restage

        // ---- stage K/V: contiguous plane copies ----
        {
            const uint32_t toff = ((uint32_t)bh * 32 + kt) * 2048;
            const uint4* skh = (const uint4*)(g_kHp + toff);
            const uint4* skl = (const uint4*)(g_kLp + toff);
            const uint4* svh = (const uint4*)(g_vHp + toff);
            const uint4* svl = (const uint4*)(g_vLp + toff);
            ((uint4*)KH)[tid] = skh[tid];  ((uint4*)KH)[256 + tid] = skh[256 + tid];
            ((uint4*)KL)[tid] = skl[tid];  ((uint4*)KL)[256 + tid] = skl[256 + tid];
            ((uint4*)VH)[tid] = svh[tid];  ((uint4*)VH)[256 + tid] = svh[256 + tid];
            ((uint4*)VL)[tid] = svl[tid];  ((uint4*)VL)[256 + tid] = svl[256 + tid];
        }
        __syncthreads();

        // ---- S = Q K^T (3-term compensated) ----
        float sS[4][4];
        #pragma unroll
        for (int nt = 0; nt < 4; nt++)
            #pragma unroll
            for (int q = 0; q < 4; q++) sS[nt][q] = 0.f;

        #pragma unroll
        for (int ks = 0; ks < 4; ks++) {
            uint4 qh4 = *(const uint4*)&QH[(ks * 4 + wr) * 128 + lp * 4];
            uint4 ql4 = *(const uint4*)&QL[(ks * 4 + wr) * 128 + lp * 4];
            const uint32_t* qh = (const uint32_t*)&qh4;
            const uint32_t* ql = (const uint32_t*)&ql4;
            const uint32_t a0 = qh[0 ^ ks], a1 = qh[1 ^ ks];
            const uint32_t a2 = qh[2 ^ ks], a3 = qh[3 ^ ks];
            const uint32_t e0 = ql[0 ^ ks], e1 = ql[1 ^ ks];
            const uint32_t e2 = ql[2 ^ ks], e3 = ql[3 ^ ks];
            const int lpb = lp ^ (ks << 3);
            #pragma unroll
            for (int ntl = 0; ntl < 4; ntl++) {
                const int nt = wc * 4 + ntl;
                uint2 kh = *(const uint2*)&KH[(ks * 8 + nt) * 64 + lpb * 2];
                uint2 kl = *(const uint2*)&KL[(ks * 8 + nt) * 64 + lpb * 2];
                mma_bf16(sS[ntl], a0, a1, a2, a3, kh.x, kh.y);
                mma_bf16(sS[ntl], e0, e1, e2, e3, kh.x, kh.y);
                mma_bf16(sS[ntl], a0, a1, a2, a3, kl.x, kl.y);
            }
        }

        // ---- online softmax ----
        float mx0 = fmaxf(fmaxf(sS[0][0], sS[0][1]), fmaxf(sS[1][0], sS[1][1]));
        mx0 = fmaxf(mx0, fmaxf(fmaxf(sS[2][0], sS[2][1]), fmaxf(sS[3][0], sS[3][1])));
        float mx1 = fmaxf(fmaxf(sS[0][2], sS[0][3]), fmaxf(sS[1][2], sS[1][3]));
        mx1 = fmaxf(mx1, fmaxf(fmaxf(sS[2][2], sS[2][3]), fmaxf(sS[3][2], sS[3][3])));
        mx0 = fmaxf(mx0, __shfl_xor_sync(0xffffffffu, mx0, 1, 32));
        mx0 = fmaxf(mx0, __shfl_xor_sync(0xffffffffu, mx0, 2, 32));
        mx1 = fmaxf(mx1, __shfl_xor_sync(0xffffffffu, mx1, 1, 32));
        mx1 = fmaxf(mx1, __shfl_xor_sync(0xffffffffu, mx1, 2, 32));
        const int r0l = wr * 16 + g;
        if (t == 0) {
            smax[wc * 64 + r0l]     = mx0;
            smax[wc * 64 + r0l + 8] = mx1;
        }
        BAR_PAIR(1 + wr);
        const float M0 = fmaxf(smax[r0l],     smax[64 + r0l]);
        const float M1 = fmaxf(smax[r0l + 8], smax[64 + r0l + 8]);
        const float mn0 = fmaxf(mrow0, M0), mn1 = fmaxf(mrow1, M1);
        const float cr0 = __expf(mrow0 - mn0), cr1 = __expf(mrow1 - mn1);
        mrow0 = mn0;  mrow1 = mn1;

        float rs0 = 0.f, rs1 = 0.f;
        #pragma unroll
        for (int nt = 0; nt < 4; nt++) {
            sS[nt][0] = __expf(sS[nt][0] - mn0);
            sS[nt][1] = __expf(sS[nt][1] - mn0);
            sS[nt][2] = __expf(sS[nt][2] - mn1);
            sS[nt][3] = __expf(sS[nt][3] - mn1);
            rs0 += sS[nt][0] + sS[nt][1];
            rs1 += sS[nt][2] + sS[nt][3];
        }
        rs0 += __shfl_xor_sync(0xffffffffu, rs0, 1, 32);
        rs0 += __shfl_xor_sync(0xffffffffu, rs0, 2, 32);
        rs1 += __shfl_xor_sync(0xffffffffu, rs1, 1, 32);
        rs1 += __shfl_xor_sync(0xffffffffu, rs1, 2, 32);
        if (t == 0) {
            ssum[wc * 64 + r0l]     = rs0;
            ssum[wc * 64 + r0l + 8] = rs1;
        }
        BAR_PAIR(1 + wr);
        lsum0 = lsum0 * cr0 + ssum[r0l]     + ssum[64 + r0l];
        lsum1 = lsum1 * cr1 + ssum[r0l + 8] + ssum[64 + r0l + 8];

        #pragma unroll
        for (int nt = 0; nt < 4; nt++) {
            O[nt][0] *= cr0;  O[nt][1] *= cr0;
            O[nt][2] *= cr1;  O[nt][3] *= cr1;
        }

        // ---- stage P from C-frags ----
        #pragma unroll
        for (int kl = 0; kl < 2; kl++) {
            const int ks = wc * 2 + kl;
            uint4 hh, ll;
            bf16_split2(sS[2*kl][0],   sS[2*kl][1],   hh.x, ll.x);
            bf16_split2(sS[2*kl][2],   sS[2*kl][3],   hh.y, ll.y);
            bf16_split2(sS[2*kl+1][0], sS[2*kl+1][1], hh.z, ll.z);
            bf16_split2(sS[2*kl+1][2], sS[2*kl+1][3], hh.w, ll.w);
            *(uint4*)&PH[(ks * 4 + wr) * 128 + lane * 4] = hh;
            *(uint4*)&PL[(ks * 4 + wr) * 128 + lane * 4] = ll;
        }
        BAR_PAIR(1 + wr);

        // ---- O += P V (3-term compensated) ----
        #pragma unroll
        for (int ks = 0; ks < 4; ks++) {
            uint4 ph4 = *(const uint4*)&PH[(ks * 4 + wr) * 128 + lane * 4];
            uint4 pl4 = *(const uint4*)&PL[(ks * 4 + wr) * 128 + lane * 4];
            #pragma unroll
            for (int ntl = 0; ntl < 4; ntl++) {
                const int nt = wc * 4 + ntl;
                const int lpv = (lp ^ (ks << 3)) ^ nt;
                uint2 vh = *(const uint2*)&VH[(ks * 8 + nt) * 64 + lpv * 2];
                uint2 vl = *(const uint2*)&VL[(ks * 8 + nt) * 64 + lpv * 2];
                mma_bf16(O[ntl], ph4.x, ph4.y, ph4.z, ph4.w, vh.x, vh.y);
                mma_bf16(O[ntl], pl4.x, pl4.y, pl4.z, pl4.w, vh.x, vh.y);
                mma_bf16(O[ntl], ph4.x, ph4.y, ph4.z, ph4.w, vl.x, vl.y);
            }
        }
    }

    // ---- normalize + write context [B,N,C] ----
    const int b = bh / NH, h = bh % NH;
    const float inv0 = 1.0f / lsum0, inv1 = 1.0f / lsum1;
    #pragma unroll
    for (int ntl = 0; ntl < 4; ntl++) {
        const int d = wc * 32 + ntl * 8 + t * 2;
        const int r0 = q0 + wr * 16 + g;
        float2 o0 = make_float2(O[ntl][0] * inv0, O[ntl][1] * inv0);
        float2 o1 = make_float2(O[ntl][2] * inv1, O[ntl][3] * inv1);
        *(float2*)&g_ctx[((size_t)(b * SEQ + r0))     * EMBED + h * HD + d] = o0;
        *(float2*)&g_ctx[((size_t)(b * SEQ + r0 + 8)) * EMBED + h * HD + d] = o1;
    }
}

// ---------------------------------------------------------------------------
extern "C" void kernel_launch(void* const* d_in, const int* in_sizes, int n_in,
                              void* d_out, int out_size)
{
    const float* x  = (const float*)d_in[0];
    const float* Wq = (const float*)d_in[1];
    const float* bq = (const float*)d_in[2];
    const float* Wk = (const float*)d_in[3];
    const float* bk = (const float*)d_in[4];
    const float* Wv = (const float*)d_in[5];
    const float* bv = (const float*)d_in[6];
    const float* Wo = (const float*)d_in[7];
    const float* bo = (const float*)d_in[8];
    float* out = (float*)d_out;

    cudaFuncSetAttribute(qkv_mma_kernel,
                         cudaFuncAttributeMaxDynamicSharedMemorySize, GEMM_SMEM);
    cudaFuncSetAttribute(out_mma_kernel,
                         cudaFuncAttributeMaxDynamicSharedMemorySize, GEMM_SMEM);
    cudaFuncSetAttribute(attn_kernel,
                         cudaFuncAttributeMaxDynamicSharedMemorySize, ATT_SMEM);

    // pre-split conversions
    conv_afrag_kernel<<<MROWS, 192>>>(x, 0);
    conv_bfrag_kernel<<<EMBED, 192>>>(Wq, 0);
    conv_bfrag_kernel<<<EMBED, 192>>>(Wk, 1);
    conv_bfrag_kernel<<<EMBED, 192>>>(Wv, 2);
    conv_bfrag_kernel<<<EMBED, 192>>>(Wo, 3);

    dim3 gq(EMBED/128, MROWS/128, 3);   // (6, 64, 3)
    qkv_mma_kernel<<<gq, 256, GEMM_SMEM>>>(bq, bk, bv);

    dim3 gkv(SEQ/64, BATCH*NH);         // (32, 48)
    conv_kv_kernel<<<gkv, 256>>>();

    attn_kernel<<<gkv, 256, ATT_SMEM>>>();

    conv_afrag_kernel<<<MROWS, 192>>>(nullptr, 1);

    dim3 go(EMBED/128, MROWS/128);      // (6, 64)
    out_mma_kernel<<<go, 256, GEMM_SMEM>>>(bo, out);
}

// round 17
// speedup vs baseline: 1.5764x; 1.0942x over previous
#include <cuda_runtime.h>
#include <math.h>
#include <stdint.h>

#define EMBED 768
#define NH    12
#define HD    64
#define BATCH 4
#define SEQ   2048
#define MROWS (BATCH*SEQ)   // 8192

// fp32 scratch
__device__ float g_q[BATCH*NH*SEQ*HD];
__device__ float g_k[BATCH*NH*SEQ*HD];
__device__ float g_v[BATCH*NH*SEQ*HD];
__device__ float g_ctx[MROWS*EMBED];

// Pre-split bf16 hi/lo planes, frag-permuted (u32 = bf16x2)
#define XPL (64*24*2048)   // A-frag planes: 64 m-tiles x 24 slabs
#define WPL (6*24*2048)    // B-frag planes: 6 n-tiles x 24 slabs
#define KPL (48*32*2048)   // attn planes: 48 bh x 32 tiles
__device__ uint32_t g_xH[XPL],  g_xL[XPL];
__device__ uint32_t g_wH4[4*WPL], g_wL4[4*WPL];
__device__ uint32_t g_cH[XPL],  g_cL[XPL];
__device__ uint32_t g_kHp[KPL], g_kLp[KPL], g_vHp[KPL], g_vLp[KPL];

typedef unsigned long long ull;

// ---------------- mma.sync bf16 helpers ----------------
__device__ __forceinline__ void bf16_split2(float x, float y,
                                            uint32_t &h2, uint32_t &l2) {
    asm("cvt.rn.bf16x2.f32 %0, %1, %2;" : "=r"(h2) : "f"(y), "f"(x));
    float hx = __uint_as_float(h2 << 16);
    float hy = __uint_as_float(h2 & 0xFFFF0000u);
    asm("cvt.rn.bf16x2.f32 %0, %1, %2;" : "=r"(l2) : "f"(y - hy), "f"(x - hx));
}
__device__ __forceinline__ void mma_bf16(float (&c)[4],
                                         uint32_t a0, uint32_t a1,
                                         uint32_t a2, uint32_t a3,
                                         uint32_t b0, uint32_t b1) {
    asm("mma.sync.aligned.m16n8k16.row.col.f32.bf16.bf16.f32 "
        "{%0,%1,%2,%3}, {%4,%5,%6,%7}, {%8,%9}, {%0,%1,%2,%3};"
        : "+f"(c[0]), "+f"(c[1]), "+f"(c[2]), "+f"(c[3])
        : "r"(a0), "r"(a1), "r"(a2), "r"(a3), "r"(b0), "r"(b1));
}
__device__ __forceinline__ void cp_async16(uint32_t saddr, const void* g) {
    asm volatile("cp.async.cg.shared.global [%0], [%1], 16;"
                 :: "r"(saddr), "l"(g) : "memory");
}
#define CP_COMMIT() asm volatile("cp.async.commit_group;" ::: "memory")
#define BAR_PAIR(id) \
    asm volatile("bar.sync %0, 64;" :: "r"(id) : "memory")

// ---------------------------------------------------------------------------
// Converters: fp32 -> frag-permuted hi/lo bf16x2 planes (unchanged, passing).
// ---------------------------------------------------------------------------
__global__ __launch_bounds__(192) void conv_afrag_kernel(
    const float* __restrict__ src_in, int which)
{
    const float* src = which ? (const float*)g_ctx : src_in;
    uint32_t* H = which ? g_cH : g_xH;
    uint32_t* L = which ? g_cL : g_xL;

    const int row_g = blockIdx.x;          // 0..8191
    const int k = threadIdx.x * 4;         // 0..764
    float4 v = *(const float4*)(src + (size_t)row_g * EMBED + k);

    const int s = k >> 5;
    const int row = row_g & 127;
    uint32_t* Hp = H + ((size_t)(row_g >> 7) * 24 + s) * 2048;
    uint32_t* Lp = L + ((size_t)(row_g >> 7) * 24 + s) * 2048;

    const int k4 = k & 31;
    const int ks = k4 >> 4, kk = k4 & 15;
    const int hk = kk >> 3, t0 = (kk & 7) >> 1;
    const int g = row & 7, hm = (row >> 3) & 1, mt = row >> 4;
    const int idx  = (hm + 2 * hk) ^ ks;
    const int base = (ks * 8 + mt) * 128 + idx;
    uint32_t h2, l2;
    bf16_split2(v.x, v.y, h2, l2);
    int sl = g * 4 + t0;  int sp = sl ^ ((sl >> 3) & 1);
    Hp[base + sp * 4] = h2;  Lp[base + sp * 4] = l2;
    bf16_split2(v.z, v.w, h2, l2);
    sl = g * 4 + t0 + 1;  sp = sl ^ ((sl >> 3) & 1);
    Hp[base + sp * 4] = h2;  Lp[base + sp * 4] = l2;
}

__global__ __launch_bounds__(192) void conv_bfrag_kernel(
    const float* __restrict__ src, int z)
{
    const int row_g = blockIdx.x;          // 0..767
    const int k = threadIdx.x * 4;
    float4 v = *(const float4*)(src + (size_t)row_g * EMBED + k);

    const int s = k >> 5;
    const int row = row_g & 127;
    const size_t po = ((size_t)z * 6 + (row_g >> 7)) * 24 + s;
    uint32_t* Hp = g_wH4 + po * 2048;
    uint32_t* Lp = g_wL4 + po * 2048;

    const int k4 = k & 31;
    const int ks = k4 >> 4, kk = k4 & 15;
    const int hk = kk >> 3, t0 = (kk & 7) >> 1;
    const int gn = row & 7, nt = row >> 3;
    const int base = (ks * 16 + nt) * 64 + hk;
    uint32_t h2, l2;
    bf16_split2(v.x, v.y, h2, l2);
    int sl = gn * 4 + t0;
    int sp = (sl ^ ((sl >> 3) & 1)) ^ (ks << 3);
    Hp[base + sp * 2] = h2;  Lp[base + sp * 2] = l2;
    bf16_split2(v.z, v.w, h2, l2);
    sl = gn * 4 + t0 + 1;
    sp = (sl ^ ((sl >> 3) & 1)) ^ (ks << 3);
    Hp[base + sp * 2] = h2;  Lp[base + sp * 2] = l2;
}

__global__ __launch_bounds__(256) void conv_kv_kernel()
{
    const int kt = blockIdx.x;             // 0..31
    const int bh = blockIdx.y;             // 0..47
    const int tid = threadIdx.x;
    const int ct = kt * 64;
    const size_t gbase = (size_t)bh * SEQ * HD;
    const uint32_t toff = ((uint32_t)bh * 32 + kt) * 2048;
    uint32_t* KH = g_kHp + toff;  uint32_t* KL = g_kLp + toff;
    uint32_t* VH = g_vHp + toff;  uint32_t* VL = g_vLp + toff;

    #pragma unroll
    for (int it = 0; it < 4; it++) {
        const int f  = it * 256 + tid;
        const int r  = f >> 4;
        const int k4 = (f & 15) * 4;
        float4 v = *(const float4*)(g_k + gbase + (size_t)(ct + r) * HD + k4);
        const int nt = r >> 3, gn = r & 7;
        const int ks = k4 >> 4, kk = k4 & 15;
        const int khalf = kk >> 3, t0 = (kk & 7) >> 1;
        const int base = (ks * 8 + nt) * 64 + khalf;
        uint32_t h2, l2;
        bf16_split2(v.x, v.y, h2, l2);
        int sl = gn * 4 + t0;
        int sp = (sl ^ ((sl >> 3) & 1)) ^ (ks << 3);
        KH[base + sp * 2] = h2;  KL[base + sp * 2] = l2;
        bf16_split2(v.z, v.w, h2, l2);
        sl = gn * 4 + t0 + 1;
        sp = (sl ^ ((sl >> 3) & 1)) ^ (ks << 3);
        KH[base + sp * 2] = h2;  KL[base + sp * 2] = l2;
    }
    #pragma unroll
    for (int it = 0; it < 2; it++) {
        const int f  = it * 256 + tid;
        const int cp = f >> 4;
        const int dq = (f & 15) * 4;
        const int c0 = cp * 2;
        float4 v0 = *(const float4*)(g_v + gbase + (size_t)(ct + c0)     * HD + dq);
        float4 v1 = *(const float4*)(g_v + gbase + (size_t)(ct + c0 + 1) * HD + dq);
        const int ks = c0 >> 4, kc = c0 & 15;
        const int khalf = kc >> 3, tt = (kc & 7) >> 1;
        const float* a0 = (const float*)&v0;
        const float* a1 = (const float*)&v1;
        #pragma unroll
        for (int j = 0; j < 4; j++) {
            const int d = dq + j;
            const int nt = d >> 3, gn = d & 7;
            const int sl = gn * 4 + tt;
            const int sp = ((sl ^ ((sl >> 3) & 1)) ^ (ks << 3)) ^ nt;
            const int addr = (ks * 8 + nt) * 64 + khalf + sp * 2;
            uint32_t h2, l2;
            bf16_split2(a0[j], a1[j], h2, l2);
            VH[addr] = h2;  VL[addr] = l2;
        }
    }
}

// ---------------------------------------------------------------------------
// Tensor-core GEMM: cp.async double-buffered plane staging (R14, passing).
// ---------------------------------------------------------------------------
#define NSLAB (EMBED/32)   // 24
#define GEMM_SMEM (2 * 8192 * 4)   // 65536 bytes

__device__ __forceinline__ void gemm_mma_slab(const uint32_t* __restrict__ SB,
                                              int wr, int wc, int lp,
                                              float C[4][4][4])
{
    const uint32_t* AH = SB;
    const uint32_t* AL = SB + 2048;
    const uint32_t* BH = SB + 4096;
    const uint32_t* BL = SB + 6144;
    #pragma unroll
    for (int ks = 0; ks < 2; ks++) {
        uint4 ah[4], al4[4];
        uint2 bh[4], bl4[4];
        #pragma unroll
        for (int mt = 0; mt < 4; mt++) {
            const int off = (ks * 8 + wr * 4 + mt) * 128 + lp * 4;
            ah[mt]  = *(const uint4*)&AH[off];
            al4[mt] = *(const uint4*)&AL[off];
        }
        const int lpb = lp ^ (ks << 3);
        #pragma unroll
        for (int nt = 0; nt < 4; nt++) {
            const int off = (ks * 16 + wc * 4 + nt) * 64 + lpb * 2;
            bh[nt]  = *(const uint2*)&BH[off];
            bl4[nt] = *(const uint2*)&BL[off];
        }
        #pragma unroll
        for (int mt = 0; mt < 4; mt++) {
            const uint32_t a0 = ks ? ah[mt].y  : ah[mt].x;
            const uint32_t a1 = ks ? ah[mt].x  : ah[mt].y;
            const uint32_t a2 = ks ? ah[mt].w  : ah[mt].z;
            const uint32_t a3 = ks ? ah[mt].z  : ah[mt].w;
            const uint32_t e0 = ks ? al4[mt].y : al4[mt].x;
            const uint32_t e1 = ks ? al4[mt].x : al4[mt].y;
            const uint32_t e2 = ks ? al4[mt].w : al4[mt].z;
            const uint32_t e3 = ks ? al4[mt].z : al4[mt].w;
            #pragma unroll
            for (int nt = 0; nt < 4; nt++) {
                mma_bf16(C[mt][nt], a0, a1, a2, a3, bh[nt].x, bh[nt].y);
                mma_bf16(C[mt][nt], e0, e1, e2, e3, bh[nt].x, bh[nt].y);
                mma_bf16(C[mt][nt], a0, a1, a2, a3, bl4[nt].x, bl4[nt].y);
            }
        }
    }
}

// Issue async copy of slab s (4 planes x 8KB) into buffer buf.
#define GEMM_PREF(s, buf) do {                                             \
    const uint32_t _sd = sbase + (buf) * 32768;                            \
    cp_async16(_sd +     0 + tid * 16, AHg + (s) * 2048 + tid * 4);        \
    cp_async16(_sd +  4096 + tid * 16, AHg + (s) * 2048 + 1024 + tid * 4); \
    cp_async16(_sd +  8192 + tid * 16, ALg + (s) * 2048 + tid * 4);        \
    cp_async16(_sd + 12288 + tid * 16, ALg + (s) * 2048 + 1024 + tid * 4); \
    cp_async16(_sd + 16384 + tid * 16, BHg + (s) * 2048 + tid * 4);        \
    cp_async16(_sd + 20480 + tid * 16, BHg + (s) * 2048 + 1024 + tid * 4); \
    cp_async16(_sd + 24576 + tid * 16, BLg + (s) * 2048 + tid * 4);        \
    cp_async16(_sd + 28672 + tid * 16, BLg + (s) * 2048 + 1024 + tid * 4); \
    CP_COMMIT();                                                           \
} while (0)

__device__ __forceinline__ void mma_gemm_mainloop_pl(
    const uint32_t* __restrict__ AHg, const uint32_t* __restrict__ ALg,
    const uint32_t* __restrict__ BHg, const uint32_t* __restrict__ BLg,
    uint32_t* __restrict__ SB, float C[4][4][4])
{
    const int tid  = threadIdx.x;
    const int lane = tid & 31;
    const int wid  = tid >> 5;
    const int wr   = wid >> 2;
    const int wc   = wid & 3;
    const int lp   = lane ^ ((lane >> 3) & 1);
    const uint32_t sbase = (uint32_t)__cvta_generic_to_shared(SB);

    GEMM_PREF(0, 0);
    #pragma unroll 1
    for (int s = 0; s < NSLAB; s++) {
        if (s + 1 < NSLAB) {
            GEMM_PREF(s + 1, (s + 1) & 1);
            asm volatile("cp.async.wait_group 1;" ::: "memory");
        } else {
            asm volatile("cp.async.wait_group 0;" ::: "memory");
        }
        __syncthreads();           // slab s visible to all warps
        gemm_mma_slab(SB + (s & 1) * 8192, wr, wc, lp, C);
        __syncthreads();           // all done with buf s&1 before s+2 prefetch
    }
}

__global__ __launch_bounds__(256) void qkv_mma_kernel(
    const float* __restrict__ bq, const float* __restrict__ bk,
    const float* __restrict__ bv)
{
    extern __shared__ uint32_t SB[];
    const int z = blockIdx.z;
    const float* bias = (z == 0) ? bq : (z == 1) ? bk : bv;
    float* dst = (z == 0) ? g_q : (z == 1) ? g_k : g_v;

    const int m0 = blockIdx.y * 128;
    const int n0 = blockIdx.x * 128;
    const uint32_t* AHg = g_xH + ((size_t)blockIdx.y * 24) * 2048;
    const uint32_t* ALg = g_xL + ((size_t)blockIdx.y * 24) * 2048;
    const size_t bo_ = (((size_t)z * 6 + blockIdx.x) * 24) * 2048;
    const uint32_t* BHg = g_wH4 + bo_;
    const uint32_t* BLg = g_wL4 + bo_;

    float C[4][4][4];
    #pragma unroll
    for (int mt = 0; mt < 4; mt++)
        #pragma unroll
        for (int nt = 0; nt < 4; nt++)
            #pragma unroll
            for (int q = 0; q < 4; q++) C[mt][nt][q] = 0.f;

    mma_gemm_mainloop_pl(AHg, ALg, BHg, BLg, SB, C);

    const int lane = threadIdx.x & 31;
    const int wid  = threadIdx.x >> 5;
    const int wr = wid >> 2, wc = wid & 3;
    const int g = lane >> 2, t = lane & 3;
    #pragma unroll
    for (int mt = 0; mt < 4; mt++) {
        #pragma unroll
        for (int nt = 0; nt < 4; nt++) {
            const int c = n0 + wc * 32 + nt * 8 + t * 2;
            const int h = c >> 6, d = c & 63;
            const float2 bv2 = *(const float2*)(bias + c);
            #pragma unroll
            for (int half = 0; half < 2; half++) {
                const int m = m0 + wr * 64 + mt * 16 + g + half * 8;
                const int b = m >> 11;
                const int n = m & 2047;
                float2 o;
                o.x = C[mt][nt][half * 2 + 0] + bv2.x;
                o.y = C[mt][nt][half * 2 + 1] + bv2.y;
                *(float2*)&dst[(((size_t)(b * NH + h) * SEQ) + n) * HD + d] = o;
            }
        }
    }
}

__global__ __launch_bounds__(256) void out_mma_kernel(
    const float* __restrict__ bo, float* __restrict__ out)
{
    extern __shared__ uint32_t SB[];
    const int m0 = blockIdx.y * 128;
    const int n0 = blockIdx.x * 128;
    const uint32_t* AHg = g_cH + ((size_t)blockIdx.y * 24) * 2048;
    const uint32_t* ALg = g_cL + ((size_t)blockIdx.y * 24) * 2048;
    const size_t bo_ = (((size_t)3 * 6 + blockIdx.x) * 24) * 2048;
    const uint32_t* BHg = g_wH4 + bo_;
    const uint32_t* BLg = g_wL4 + bo_;

    float C[4][4][4];
    #pragma unroll
    for (int mt = 0; mt < 4; mt++)
        #pragma unroll
        for (int nt = 0; nt < 4; nt++)
            #pragma unroll
            for (int q = 0; q < 4; q++) C[mt][nt][q] = 0.f;

    mma_gemm_mainloop_pl(AHg, ALg, BHg, BLg, SB, C);

    const int lane = threadIdx.x & 31;
    const int wid  = threadIdx.x >> 5;
    const int wr = wid >> 2, wc = wid & 3;
    const int g = lane >> 2, t = lane & 3;
    #pragma unroll
    for (int mt = 0; mt < 4; mt++) {
        #pragma unroll
        for (int nt = 0; nt < 4; nt++) {
            const int c = n0 + wc * 32 + nt * 8 + t * 2;
            const float2 bv2 = *(const float2*)(bo + c);
            #pragma unroll
            for (int half = 0; half < 2; half++) {
                const int m = m0 + wr * 64 + mt * 16 + g + half * 8;
                float2 o;
                o.x = C[mt][nt][half * 2 + 0] + bv2.x;
                o.y = C[mt][nt][half * 2 + 1] + bv2.y;
                *(float2*)&out[(size_t)m * EMBED + c] = o;
            }
        }
    }
}

// ---------------------------------------------------------------------------
// Flash attention (R12 math) + cp.async double-buffered K/V plane staging.
// smem (u32): QH 0 | QL 2048 | PH 4096 | PL 6144 | smax 8192 | ssum 8320
//             | KV buf0 @8448 | KV buf1 @16640  (each: KH,KL,VH,VL x2048)
// Total 24832 u32 = 99328 B; 2 CTAs/SM = 198656 B < 228 KB.
// ---------------------------------------------------------------------------
#define ATT_KV0 8448
#define ATT_SMEM ((ATT_KV0 + 2*8192) * 4)   // 99328 bytes

#define ATT_PREF(kt, buf) do {                                               \
    const uint32_t _toff = ((uint32_t)bh * 32 + (kt)) * 2048;                \
    const uint32_t _sd = sbase + (ATT_KV0 + (buf) * 8192) * 4;               \
    cp_async16(_sd +     0 + tid * 16, g_kHp + _toff + tid * 4);             \
    cp_async16(_sd +  4096 + tid * 16, g_kHp + _toff + 1024 + tid * 4);      \
    cp_async16(_sd +  8192 + tid * 16, g_kLp + _toff + tid * 4);             \
    cp_async16(_sd + 12288 + tid * 16, g_kLp + _toff + 1024 + tid * 4);      \
    cp_async16(_sd + 16384 + tid * 16, g_vHp + _toff + tid * 4);             \
    cp_async16(_sd + 20480 + tid * 16, g_vHp + _toff + 1024 + tid * 4);      \
    cp_async16(_sd + 24576 + tid * 16, g_vLp + _toff + tid * 4);             \
    cp_async16(_sd + 28672 + tid * 16, g_vLp + _toff + 1024 + tid * 4);      \
    CP_COMMIT();                                                             \
} while (0)

__global__ __launch_bounds__(256, 2) void attn_kernel()
{
    extern __shared__ uint32_t smu[];
    uint32_t* QH = smu;
    uint32_t* QL = smu + 2048;
    uint32_t* PH = smu + 4096;
    uint32_t* PL = smu + 6144;
    float* smax  = (float*)(smu + 8192);    // [2][64]
    float* ssum  = smax + 128;              // [2][64]

    const int tid  = threadIdx.x;
    const int lane = tid & 31;
    const int wid  = tid >> 5;
    const int wr   = wid >> 1;
    const int wc   = wid & 1;
    const int g    = lane >> 2;
    const int t    = lane & 3;
    const int lp   = lane ^ ((lane >> 3) & 1);

    const int bh = blockIdx.y;
    const int q0 = blockIdx.x * 64;
    const size_t gbase = (size_t)bh * SEQ * HD;
    const float* Qg = g_q + gbase;
    const uint32_t sbase = (uint32_t)__cvta_generic_to_shared(smu);

    // prefetch K/V tile 0 (overlaps Q staging)
    ATT_PREF(0, 0);

    // ---- stage Q once (A-frag layout, 0.125 scale folded in) ----
    #pragma unroll
    for (int it = 0; it < 4; it++) {
        const int f  = it * 256 + tid;
        const int r  = f >> 4;
        const int dq = (f & 15) * 4;
        float4 v = *(const float4*)(Qg + (size_t)(q0 + r) * HD + dq);
        v.x *= 0.125f; v.y *= 0.125f; v.z *= 0.125f; v.w *= 0.125f;
        const int mt = r >> 4, row = r & 15;
        const int gg = row & 7, hm = row >> 3;
        const int ks = dq >> 4, kk = dq & 15;
        const int khalf = kk >> 3, t0 = (kk & 7) >> 1;
        const int idx  = (hm + 2 * khalf) ^ ks;
        const int base = (ks * 4 + mt) * 128 + idx;
        uint32_t h2, l2;
        bf16_split2(v.x, v.y, h2, l2);
        int sl = gg * 4 + t0;  int sp = sl ^ ((sl >> 3) & 1);
        QH[base + sp * 4] = h2;  QL[base + sp * 4] = l2;
        bf16_split2(v.z, v.w, h2, l2);
        sl = gg * 4 + t0 + 1;  sp = sl ^ ((sl >> 3) & 1);
        QH[base + sp * 4] = h2;  QL[base + sp * 4] = l2;
    }

    float O[4][4];
    #pragma unroll
    for (int nt = 0; nt < 4; nt++)
        #pragma unroll
        for (int q = 0; q < 4; q++) O[nt][q] = 0.f;
    float mrow0 = -1e30f, mrow1 = -1e30f, lsum0 = 0.f, lsum1 = 0.f;

    #pragma unroll 1
    for (int kt = 0; kt < SEQ / 64; kt++) {
        __syncthreads();   // all warps done with prev compute (buf (kt+1)&1 free)

        if (kt + 1 < SEQ / 64) {
            ATT_PREF(kt + 1, (kt + 1) & 1);
            asm volatile("cp.async.wait_group 1;" ::: "memory");
        } else {
            asm volatile("cp.async.wait_group 0;" ::: "memory");
        }
        __syncthreads();   // tile kt visible block-wide

        const uint32_t* KB = smu + ATT_KV0 + (kt & 1) * 8192;
        const uint32_t* KH = KB;
        const uint32_t* KL = KB + 2048;
        const uint32_t* VH = KB + 4096;
        const uint32_t* VL = KB + 6144;

        // ---- S = Q K^T (3-term compensated) ----
        float sS[4][4];
        #pragma unroll
        for (int nt = 0; nt < 4; nt++)
            #pragma unroll
            for (int q = 0; q < 4; q++) sS[nt][q] = 0.f;

        #pragma unroll
        for (int ks = 0; ks < 4; ks++) {
            uint4 qh4 = *(const uint4*)&QH[(ks * 4 + wr) * 128 + lp * 4];
            uint4 ql4 = *(const uint4*)&QL[(ks * 4 + wr) * 128 + lp * 4];
            const uint32_t* qh = (const uint32_t*)&qh4;
            const uint32_t* ql = (const uint32_t*)&ql4;
            const uint32_t a0 = qh[0 ^ ks], a1 = qh[1 ^ ks];
            const uint32_t a2 = qh[2 ^ ks], a3 = qh[3 ^ ks];
            const uint32_t e0 = ql[0 ^ ks], e1 = ql[1 ^ ks];
            const uint32_t e2 = ql[2 ^ ks], e3 = ql[3 ^ ks];
            const int lpb = lp ^ (ks << 3);
            #pragma unroll
            for (int ntl = 0; ntl < 4; ntl++) {
                const int nt = wc * 4 + ntl;
                uint2 kh = *(const uint2*)&KH[(ks * 8 + nt) * 64 + lpb * 2];
                uint2 kl = *(const uint2*)&KL[(ks * 8 + nt) * 64 + lpb * 2];
                mma_bf16(sS[ntl], a0, a1, a2, a3, kh.x, kh.y);
                mma_bf16(sS[ntl], e0, e1, e2, e3, kh.x, kh.y);
                mma_bf16(sS[ntl], a0, a1, a2, a3, kl.x, kl.y);
            }
        }

        // ---- online softmax ----
        float mx0 = fmaxf(fmaxf(sS[0][0], sS[0][1]), fmaxf(sS[1][0], sS[1][1]));
        mx0 = fmaxf(mx0, fmaxf(fmaxf(sS[2][0], sS[2][1]), fmaxf(sS[3][0], sS[3][1])));
        float mx1 = fmaxf(fmaxf(sS[0][2], sS[0][3]), fmaxf(sS[1][2], sS[1][3]));
        mx1 = fmaxf(mx1, fmaxf(fmaxf(sS[2][2], sS[2][3]), fmaxf(sS[3][2], sS[3][3])));
        mx0 = fmaxf(mx0, __shfl_xor_sync(0xffffffffu, mx0, 1, 32));
        mx0 = fmaxf(mx0, __shfl_xor_sync(0xffffffffu, mx0, 2, 32));
        mx1 = fmaxf(mx1, __shfl_xor_sync(0xffffffffu, mx1, 1, 32));
        mx1 = fmaxf(mx1, __shfl_xor_sync(0xffffffffu, mx1, 2, 32));
        const int r0l = wr * 16 + g;
        if (t == 0) {
            smax[wc * 64 + r0l]     = mx0;
            smax[wc * 64 + r0l + 8] = mx1;
        }
        BAR_PAIR(1 + wr);
        const float M0 = fmaxf(smax[r0l],     smax[64 + r0l]);
        const float M1 = fmaxf(smax[r0l + 8], smax[64 + r0l + 8]);
        const float mn0 = fmaxf(mrow0, M0), mn1 = fmaxf(mrow1, M1);
        const float cr0 = __expf(mrow0 - mn0), cr1 = __expf(mrow1 - mn1);
        mrow0 = mn0;  mrow1 = mn1;

        float rs0 = 0.f, rs1 = 0.f;
        #pragma unroll
        for (int nt = 0; nt < 4; nt++) {
            sS[nt][0] = __expf(sS[nt][0] - mn0);
            sS[nt][1] = __expf(sS[nt][1] - mn0);
            sS[nt][2] = __expf(sS[nt][2] - mn1);
            sS[nt][3] = __expf(sS[nt][3] - mn1);
            rs0 += sS[nt][0] + sS[nt][1];
            rs1 += sS[nt][2] + sS[nt][3];
        }
        rs0 += __shfl_xor_sync(0xffffffffu, rs0, 1, 32);
        rs0 += __shfl_xor_sync(0xffffffffu, rs0, 2, 32);
        rs1 += __shfl_xor_sync(0xffffffffu, rs1, 1, 32);
        rs1 += __shfl_xor_sync(0xffffffffu, rs1, 2, 32);
        if (t == 0) {
            ssum[wc * 64 + r0l]     = rs0;
            ssum[wc * 64 + r0l + 8] = rs1;
        }
        BAR_PAIR(1 + wr);
        lsum0 = lsum0 * cr0 + ssum[r0l]     + ssum[64 + r0l];
        lsum1 = lsum1 * cr1 + ssum[r0l + 8] + ssum[64 + r0l + 8];

        #pragma unroll
        for (int nt = 0; nt < 4; nt++) {
            O[nt][0] *= cr0;  O[nt][1] *= cr0;
            O[nt][2] *= cr1;  O[nt][3] *= cr1;
        }

        // ---- stage P from C-frags ----
        #pragma unroll
        for (int kl = 0; kl < 2; kl++) {
            const int ks = wc * 2 + kl;
            uint4 hh, ll;
            bf16_split2(sS[2*kl][0],   sS[2*kl][1],   hh.x, ll.x);
            bf16_split2(sS[2*kl][2],   sS[2*kl][3],   hh.y, ll.y);
            bf16_split2(sS[2*kl+1][0], sS[2*kl+1][1], hh.z, ll.z);
            bf16_split2(sS[2*kl+1][2], sS[2*kl+1][3], hh.w, ll.w);
            *(uint4*)&PH[(ks * 4 + wr) * 128 + lane * 4] = hh;
            *(uint4*)&PL[(ks * 4 + wr) * 128 + lane * 4] = ll;
        }
        BAR_PAIR(1 + wr);

        // ---- O += P V (3-term compensated) ----
        #pragma unroll
        for (int ks = 0; ks < 4; ks++) {
            uint4 ph4 = *(const uint4*)&PH[(ks * 4 + wr) * 128 + lane * 4];
            uint4 pl4 = *(const uint4*)&PL[(ks * 4 + wr) * 128 + lane * 4];
            #pragma unroll
            for (int ntl = 0; ntl < 4; ntl++) {
                const int nt = wc * 4 + ntl;
                const int lpv = (lp ^ (ks << 3)) ^ nt;
                uint2 vh = *(const uint2*)&VH[(ks * 8 + nt) * 64 + lpv * 2];
                uint2 vl = *(const uint2*)&VL[(ks * 8 + nt) * 64 + lpv * 2];
                mma_bf16(O[ntl], ph4.x, ph4.y, ph4.z, ph4.w, vh.x, vh.y);
                mma_bf16(O[ntl], pl4.x, pl4.y, pl4.z, pl4.w, vh.x, vh.y);
                mma_bf16(O[ntl], ph4.x, ph4.y, ph4.z, ph4.w, vl.x, vl.y);
            }
        }
    }

    // ---- normalize + write context [B,N,C] ----
    const int b = bh / NH, h = bh % NH;
    const float inv0 = 1.0f / lsum0, inv1 = 1.0f / lsum1;
    #pragma unroll
    for (int ntl = 0; ntl < 4; ntl++) {
        const int d = wc * 32 + ntl * 8 + t * 2;
        const int r0 = q0 + wr * 16 + g;
        float2 o0 = make_float2(O[ntl][0] * inv0, O[ntl][1] * inv0);
        float2 o1 = make_float2(O[ntl][2] * inv1, O[ntl][3] * inv1);
        *(float2*)&g_ctx[((size_t)(b * SEQ + r0))     * EMBED + h * HD + d] = o0;
        *(float2*)&g_ctx[((size_t)(b * SEQ + r0 + 8)) * EMBED + h * HD + d] = o1;
    }
}

// ---------------------------------------------------------------------------
extern "C" void kernel_launch(void* const* d_in, const int* in_sizes, int n_in,
                              void* d_out, int out_size)
{
    const float* x  = (const float*)d_in[0];
    const float* Wq = (const float*)d_in[1];
    const float* bq = (const float*)d_in[2];
    const float* Wk = (const float*)d_in[3];
    const float* bk = (const float*)d_in[4];
    const float* Wv = (const float*)d_in[5];
    const float* bv = (const float*)d_in[6];
    const float* Wo = (const float*)d_in[7];
    const float* bo = (const float*)d_in[8];
    float* out = (float*)d_out;

    cudaFuncSetAttribute(qkv_mma_kernel,
                         cudaFuncAttributeMaxDynamicSharedMemorySize, GEMM_SMEM);
    cudaFuncSetAttribute(out_mma_kernel,
                         cudaFuncAttributeMaxDynamicSharedMemorySize, GEMM_SMEM);
    cudaFuncSetAttribute(attn_kernel,
                         cudaFuncAttributeMaxDynamicSharedMemorySize, ATT_SMEM);

    // pre-split conversions
    conv_afrag_kernel<<<MROWS, 192>>>(x, 0);
    conv_bfrag_kernel<<<EMBED, 192>>>(Wq, 0);
    conv_bfrag_kernel<<<EMBED, 192>>>(Wk, 1);
    conv_bfrag_kernel<<<EMBED, 192>>>(Wv, 2);
    conv_bfrag_kernel<<<EMBED, 192>>>(Wo, 3);

    dim3 gq(EMBED/128, MROWS/128, 3);   // (6, 64, 3)
    qkv_mma_kernel<<<gq, 256, GEMM_SMEM>>>(bq, bk, bv);

    dim3 gkv(SEQ/64, BATCH*NH);         // (32, 48)
    conv_kv_kernel<<<gkv, 256>>>();

    attn_kernel<<<gkv, 256, ATT_SMEM>>>();

    conv_afrag_kernel<<<MROWS, 192>>>(nullptr, 1);

    dim3 go(EMBED/128, MROWS/128);      // (6, 64)
    out_mma_kernel<<<go, 256, GEMM_SMEM>>>(bo, out);
}